// round 12
// baseline (speedup 1.0000x reference)
#include <cuda_runtime.h>
#include <cstdint>

#define FULLMASK 0xffffffffu
typedef unsigned long long ull;

constexpr int Bb = 4;
constexpr int N1 = 8192, S1 = 2048, K1 = 32, C1 = 128;
constexpr int N2 = 2048, S2 = 256,  K2 = 16, C2 = 693;
constexpr int SMAX = 693;
constexpr int NCELL = 512;       // 8x8x8 spatial cells
constexpr int TFP = 512;         // FPS1 threads
constexpr int NCH = 128;         // chunks of 64 sorted points
constexpr int CHPW = 8;          // chunks per warp (16 warps)

// ------------- static device scratch (no runtime allocation allowed) -------------
__device__ float4 g_pack1[Bb * N1];     // (x,y,z,||p||^2) level-1 coords
__device__ float4 g_spts[Bb * N1];      // spatially sorted (x,y,z,oidx-bits)
__device__ int    g_hist[Bb * NCELL];
__device__ int    g_cellofs[Bb * NCELL];
__device__ float4 g_cent1[Bb * S1];     // l1 centers (= l1_xyz), with norms
__device__ float4 g_cent2[Bb * S2];     // l2 centers
__device__ int    g_fps1[Bb * S1];
__device__ int    g_fps2[Bb * S2];
__device__ int    g_ball1[Bb * S1 * K1];
__device__ int    g_ball2[Bb * S2 * K2];
__device__ float  g_h2[(size_t)Bb * S2 * K2 * C2];   // ~45 MB
__device__ float  g_l1pts[(size_t)Bb * S1 * C1];
__device__ double g_sums[2 * SMAX];
__device__ float  g_mu[SMAX];
__device__ float  g_rs[SMAX];

// ---------------- packed f32x2 helpers (each lane = IEEE rn op, identical to scalar) ----------------
__device__ __forceinline__ ull pk2(float a, float b) {
    ull r; asm("mov.b64 %0,{%1,%2};" : "=l"(r) : "f"(a), "f"(b)); return r;
}
__device__ __forceinline__ void upk2(ull v, float& a, float& b) {
    asm("mov.b64 {%0,%1},%2;" : "=f"(a), "=f"(b) : "l"(v));
}
__device__ __forceinline__ ull f2add(ull a, ull b) {
    ull r; asm("add.rn.f32x2 %0,%1,%2;" : "=l"(r) : "l"(a), "l"(b)); return r;
}
__device__ __forceinline__ ull f2mul(ull a, ull b) {
    ull r; asm("mul.rn.f32x2 %0,%1,%2;" : "=l"(r) : "l"(a), "l"(b)); return r;
}

// (x^2 + y^2) + z^2 with explicit rounding (no FMA contraction) — matches
// XLA's elementwise mul + sequential axis(-1) reduce.
__device__ __forceinline__ float sq3(float x, float y, float z) {
    return __fadd_rn(__fadd_rn(__fmul_rn(x, x), __fmul_rn(y, y)), __fmul_rn(z, z));
}

// ---------------- pack coords + squared norm ----------------
__global__ void k_pack1(const float* __restrict__ xyz, float4* __restrict__ pack) {
    int i = blockIdx.x * blockDim.x + threadIdx.x;
    if (i >= Bb * N1) return;
    float x = xyz[(size_t)i * 6 + 0];
    float y = xyz[(size_t)i * 6 + 1];
    float z = xyz[(size_t)i * 6 + 2];
    pack[i] = make_float4(x, y, z, sq3(x, y, z));
}

// ---------------- spatial counting sort (cells 8x8x8 over [0,1)^3) ----------------
__device__ __forceinline__ int cell_of(float x, float y, float z) {
    int cx = min(7, max(0, (int)(x * 8.0f)));
    int cy = min(7, max(0, (int)(y * 8.0f)));
    int cz = min(7, max(0, (int)(z * 8.0f)));
    return (cx << 6) | (cy << 3) | cz;
}
__global__ void k_zeroh() {
    int i = blockIdx.x * blockDim.x + threadIdx.x;
    if (i < Bb * NCELL) g_hist[i] = 0;
}
__global__ void k_cellhist(const float4* __restrict__ pack) {
    int i = blockIdx.x * blockDim.x + threadIdx.x;
    if (i >= Bb * N1) return;
    float4 v = pack[i];
    atomicAdd(&g_hist[(i / N1) * NCELL + cell_of(v.x, v.y, v.z)], 1);
}
__global__ void k_cellscan() {
    __shared__ int s[NCELL];
    int b = blockIdx.x, t = threadIdx.x;
    int h = g_hist[b * NCELL + t];
    s[t] = h;
    __syncthreads();
    for (int off = 1; off < NCELL; off <<= 1) {
        int v = (t >= off) ? s[t - off] : 0;
        __syncthreads();
        s[t] += v;
        __syncthreads();
    }
    g_cellofs[b * NCELL + t] = s[t] - h;   // exclusive prefix
}
__global__ void k_scatter(const float4* __restrict__ pack, float4* __restrict__ spts) {
    int i = blockIdx.x * blockDim.x + threadIdx.x;
    if (i >= Bb * N1) return;
    int b = i / N1;
    float4 v = pack[i];
    int pos = atomicAdd(&g_cellofs[b * NCELL + cell_of(v.x, v.y, v.z)], 1);
    spts[b * N1 + pos] = make_float4(v.x, v.y, v.z, __int_as_float(i - b * N1));
}

// ---------------- FPS level 1: single CTA per batch with value-safe chunk pruning ----------------
// Points spatially sorted into 128 chunks of 64. Per chunk we cache
// (max dd, argmax) packed as u64 = (valbits<<32) | (0x3ffffff - (oidx<<13|pos)).
// A chunk is skipped iff dist^2(centroid, chunk bbox) * 0.998 > cached max:
// then every min() in it would be a no-op, so skipping is BIT-EXACT (the
// 0.2% margin dominates all float rounding, ~1e-6 rel). dd math itself is
// the reference's no-FMA sub/mul/add chain in packed f32x2.
// u64 max over caches == max value, ties -> lowest ORIG index (jnp.argmax).
__global__ void __launch_bounds__(TFP) k_fpsp(const float4* __restrict__ spts,
                                              int* __restrict__ outIdx) {
    constexpr int N = N1, S = S1, T = TFP;
    constexpr int NW = T / 32;
    extern __shared__ float sm[];
    float* sx = sm;
    float* sy = sm + N;
    float* sz = sm + 2 * N;
    int*   soidx = (int*)(sm + 3 * N);
    float* cbox = (float*)(soidx + N);          // [NCH][6] xmn,xmx,ymn,ymx,zmn,zmx
    ull*   cache = (ull*)(cbox + NCH * 6);      // [NCH]
    __shared__ ull swv[2][NW];
    __shared__ int s_f0;

    int b = blockIdx.x, t = threadIdx.x;
    int w = t >> 5, l = t & 31;
    const float4* p = spts + (size_t)b * N;

    // mirror sorted coords + orig indices; locate orig index 0
    for (int i = t; i < N; i += T) {
        float4 v = p[i];
        sx[i] = v.x; sy[i] = v.y; sz[i] = v.z;
        int oi = __float_as_int(v.w);
        soidx[i] = oi;
        if (oi == 0) s_f0 = i;
    }
    for (int i = t; i < NCH; i += T)
        cache[i] = ((ull)__float_as_uint(1e10f)) << 32;   // forces dirty on iter 0
    __syncthreads();

    // register-owned coords: lane l of warp w holds pts (cid*64+l, cid*64+32+l)
    ull px2[CHPW], py2[CHPW], pz2[CHPW];
    float dda[CHPW], ddb[CHPW];
#pragma unroll
    for (int j = 0; j < CHPW; j++) {
        int cid = w * CHPW + j;
        int p0 = cid * 64 + l, p1 = p0 + 32;
        float x0 = sx[p0], x1 = sx[p1];
        float y0 = sy[p0], y1 = sy[p1];
        float z0 = sz[p0], z1 = sz[p1];
        px2[j] = pk2(x0, x1); py2[j] = pk2(y0, y1); pz2[j] = pk2(z0, z1);
        dda[j] = 1e10f; ddb[j] = 1e10f;
        // chunk bbox via warp redux on nonneg float bits
        unsigned xmn = __reduce_min_sync(FULLMASK, min(__float_as_uint(x0), __float_as_uint(x1)));
        unsigned xmx = __reduce_max_sync(FULLMASK, max(__float_as_uint(x0), __float_as_uint(x1)));
        unsigned ymn = __reduce_min_sync(FULLMASK, min(__float_as_uint(y0), __float_as_uint(y1)));
        unsigned ymx = __reduce_max_sync(FULLMASK, max(__float_as_uint(y0), __float_as_uint(y1)));
        unsigned zmn = __reduce_min_sync(FULLMASK, min(__float_as_uint(z0), __float_as_uint(z1)));
        unsigned zmx = __reduce_max_sync(FULLMASK, max(__float_as_uint(z0), __float_as_uint(z1)));
        if (l == 0) {
            float* cb = cbox + cid * 6;
            cb[0] = __uint_as_float(xmn); cb[1] = __uint_as_float(xmx);
            cb[2] = __uint_as_float(ymn); cb[3] = __uint_as_float(ymx);
            cb[4] = __uint_as_float(zmn); cb[5] = __uint_as_float(zmx);
        }
    }
    __syncthreads();

    int* oi = outIdx + b * S;
    int f = s_f0;       // sorted position of orig index 0
    int wo = 0;         // orig index to emit
    for (int it = 0; it < S; ++it) {
        if (t == 0) oi[it] = wo;
        float cx = sx[f], cy = sy[f], cz = sz[f];
        ull ncx = pk2(-cx, -cx), ncy = pk2(-cy, -cy), ncz = pk2(-cz, -cz);

        // bbox test: lanes test this warp's 8 chunks in parallel
        unsigned dmask;
        {
            int cid = w * CHPW + (l & 7);
            const float* cb = cbox + cid * 6;
            float dx = fmaxf(fmaxf(cb[0] - cx, cx - cb[1]), 0.0f);
            float dy = fmaxf(fmaxf(cb[2] - cy, cy - cb[3]), 0.0f);
            float dz = fmaxf(fmaxf(cb[4] - cz, cz - cb[5]), 0.0f);
            float dmin2 = dx * dx + dy * dy + dz * dz;
            float cm = __uint_as_float((unsigned)(cache[cid] >> 32));
            bool dirty = !(dmin2 * 0.998f > cm);
            dmask = __ballot_sync(FULLMASK, (l < 8) && dirty) & 0xffu;
        }

#pragma unroll
        for (int j = 0; j < CHPW; j++) {
            if (dmask & (1u << j)) {
                ull dx = f2add(px2[j], ncx);
                ull dy = f2add(py2[j], ncy);
                ull dz = f2add(pz2[j], ncz);
                ull s = f2add(f2add(f2mul(dx, dx), f2mul(dy, dy)), f2mul(dz, dz));
                float d0, d1; upk2(s, d0, d1);
                float n0 = fminf(dda[j], d0);
                float n1 = fminf(ddb[j], d1);
                dda[j] = n0; ddb[j] = n1;
                unsigned mm = __reduce_max_sync(FULLMASK,
                    max(__float_as_uint(n0), __float_as_uint(n1)));
                int cid = w * CHPW + j;
                int base = cid * 64 + l;
                unsigned cand = 0x7fffffffu;
                if (__float_as_uint(n1) == mm)
                    cand = ((unsigned)soidx[base + 32] << 13) | (unsigned)(base + 32);
                if (__float_as_uint(n0) == mm) {
                    unsigned c0 = ((unsigned)soidx[base] << 13) | (unsigned)base;
                    cand = min(cand, c0);
                }
                cand = __reduce_min_sync(FULLMASK, cand);
                if (l == 0)
                    cache[cid] = ((ull)mm << 32) | (ull)(0x3ffffffu - cand);
            }
        }

        // fold this warp's 8 caches (lanes 0..7), then block-level reduce
        ull v = (l < 8) ? cache[w * CHPW + l] : 0ull;
        v = max(v, __shfl_down_sync(FULLMASK, v, 4));
        v = max(v, __shfl_down_sync(FULLMASK, v, 2));
        v = max(v, __shfl_down_sync(FULLMASK, v, 1));
        int par = it & 1;
        if (l == 0) swv[par][w] = v;
        __syncthreads();
        ull u = (l < NW) ? swv[par][l] : 0ull;
#pragma unroll
        for (int off = 16; off >= 1; off >>= 1)
            u = max(u, __shfl_xor_sync(FULLMASK, u, off));
        unsigned rec = 0x3ffffffu - (unsigned)(u & 0x3ffffffu);
        f = (int)(rec & 0x1fffu);
        wo = (int)(rec >> 13);
    }
}

// ---------------- FPS (single CTA per batch) — level 2 ----------------
template <int N, int S, int T, int PPT>
__global__ void __launch_bounds__(T) k_fps(const float4* __restrict__ pack,
                                           int* __restrict__ outIdx) {
    extern __shared__ float sm[];
    float* sx = sm; float* sy = sm + N; float* sz = sm + 2 * N;
    __shared__ unsigned sv[2][32];
    __shared__ int si[2][32];
    constexpr int NP = PPT / 2;
    constexpr int NW = T / 32;
    int b = blockIdx.x, t = threadIdx.x;
    const float4* p = pack + (size_t)b * N;

    ull px2[NP], py2[NP], pz2[NP];
    float dd[PPT];
    {
        float pxs[PPT], pys[PPT], pzs[PPT];
#pragma unroll
        for (int j = 0; j < PPT; j++) {
            int i = t + j * T;
            float4 v = p[i];
            sx[i] = v.x; sy[i] = v.y; sz[i] = v.z;
            pxs[j] = v.x; pys[j] = v.y; pzs[j] = v.z;
            dd[j] = 1e10f;
        }
#pragma unroll
        for (int q = 0; q < NP; q++) {
            px2[q] = pk2(pxs[2 * q], pxs[2 * q + 1]);
            py2[q] = pk2(pys[2 * q], pys[2 * q + 1]);
            pz2[q] = pk2(pzs[2 * q], pzs[2 * q + 1]);
        }
    }
    __syncthreads();

    int* oi = outIdx + b * S;
    int lane = t & 31, wid = t >> 5;
    int f = 0;
    for (int it = 0; it < S; ++it) {
        if (t == 0) oi[it] = f;
        float cx = sx[f], cy = sy[f], cz = sz[f];
        ull ncx = pk2(-cx, -cx), ncy = pk2(-cy, -cy), ncz = pk2(-cz, -cz);
        float m = __int_as_float(0xff800000);
#pragma unroll
        for (int q = 0; q < NP; q++) {
            ull dx = f2add(px2[q], ncx);
            ull dy = f2add(py2[q], ncy);
            ull dz = f2add(pz2[q], ncz);
            ull s = f2add(f2add(f2mul(dx, dx), f2mul(dy, dy)), f2mul(dz, dz));
            float lo, hi; upk2(s, lo, hi);
            float n0 = fminf(dd[2 * q], lo);
            float n1 = fminf(dd[2 * q + 1], hi);
            dd[2 * q] = n0; dd[2 * q + 1] = n1;
            m = fmaxf(m, fmaxf(n0, n1));
        }
        unsigned mbv = __float_as_uint(m);
        unsigned wmax = __reduce_max_sync(FULLMASK, mbv);
        int cand = 0x7fffffff;
        if (mbv == wmax) {
#pragma unroll
            for (int j = PPT - 1; j >= 0; j--)
                if (__float_as_uint(dd[j]) == wmax) cand = t + j * T;
        }
        int wi = __reduce_min_sync(FULLMASK, cand);
        int par = it & 1;
        if (lane == 0) { sv[par][wid] = wmax; si[par][wid] = wi; }
        __syncthreads();
        unsigned u2 = (lane < NW) ? sv[par][lane] : 0u;
        int i2 = (lane < NW) ? si[par][lane] : 0x7fffffff;
        unsigned m2 = __reduce_max_sync(FULLMASK, u2);
        f = __reduce_min_sync(FULLMASK, (u2 == m2) ? i2 : 0x7fffffff);
    }
}

// ---------------- gather sampled centers (and optionally emit l2_xyz) ----------------
__global__ void k_gather(const float4* __restrict__ pack, const int* __restrict__ fps,
                         float4* __restrict__ cent, int S, int N,
                         float* __restrict__ xyzOut) {
    int i = blockIdx.x * blockDim.x + threadIdx.x;
    if (i >= Bb * S) return;
    int b = i / S;
    float4 v = pack[b * N + fps[i]];
    cent[i] = v;
    if (xyzOut) {
        xyzOut[(size_t)i * 3 + 0] = v.x;
        xyzOut[(size_t)i * 3 + 1] = v.y;
        xyzOut[(size_t)i * 3 + 2] = v.z;
    }
}

// ---------------- ball query: one warp per center ----------------
template <int NPTS, int K>
__global__ void k_ball(const float4* __restrict__ pack, const float4* __restrict__ cent,
                       int S, float r2, int* __restrict__ out) {
    int lane = threadIdx.x & 31;
    int cid = (blockIdx.x * blockDim.x + threadIdx.x) >> 5;
    if (cid >= Bb * S) return;
    int b = cid / S;
    float4 c = cent[cid];
    const float4* p = pack + (size_t)b * NPTS;
    int* o = out + (size_t)cid * K;
    int cnt = 0, first = -1;
    for (int base = 0; base < NPTS && cnt < K; base += 128) {
        float4 q[4];
#pragma unroll
        for (int u = 0; u < 4; u++) q[u] = p[base + u * 32 + lane];
#pragma unroll
        for (int u = 0; u < 4; u++) {
            float dot = fmaf(c.z, q[u].z, fmaf(c.y, q[u].y, __fmul_rn(c.x, q[u].x)));
            float sq = __fsub_rn(__fadd_rn(c.w, q[u].w), __fmul_rn(2.0f, dot));
            bool in = !(sq > r2);
            unsigned bm = __ballot_sync(FULLMASK, in);
            if (bm) {
                int pos = cnt + __popc(bm & ((1u << lane) - 1u));
                if (in && pos < K) o[pos] = base + u * 32 + lane;
                if (first < 0) first = base + u * 32 + __ffs(bm) - 1;
                cnt += __popc(bm);
            }
        }
    }
    if (first < 0) first = NPTS - 1;   // empty ball: idx n, clamped at gather
    for (int pos = min(cnt, K) + lane; pos < K; pos += 32) o[pos] = first;
}

// ---------------- zero the BN accumulators ----------------
__global__ void k_zero() {
    int i = blockIdx.x * blockDim.x + threadIdx.x;
    if (i < 2 * SMAX) g_sums[i] = 0.0;
}

// ---------------- level-1 feature gather (shared by both passes) ----------------
__device__ __forceinline__ void l1_gather(float* F, const float* __restrict__ xyz,
                                          int bs, int b, int t) {
    if (t < K1) {
        int idx = g_ball1[bs * K1 + t];
        float4 p = g_pack1[b * N1 + idx];
        float4 c = g_cent1[bs];
        const float* nr = xyz + (size_t)(b * N1 + idx) * 6 + 3;
        F[t * 6 + 0] = __fsub_rn(p.x, c.x);
        F[t * 6 + 1] = __fsub_rn(p.y, c.y);
        F[t * 6 + 2] = __fsub_rn(p.z, c.z);
        F[t * 6 + 3] = nr[0];
        F[t * 6 + 4] = nr[1];
        F[t * 6 + 5] = nr[2];
    }
}

__device__ __forceinline__ float l1_h(const float* fv, const float* w, float bias) {
    float h = fmaf(fv[0], w[0], 0.0f);
#pragma unroll
    for (int j = 1; j < 6; j++) h = fmaf(fv[j], w[j], h);
    return __fadd_rn(h, bias);
}

// ---------------- level-1 MLP pass A: statistics only ----------------
__global__ void k_mlp1(const float* __restrict__ xyz,
                       const float* __restrict__ w1, const float* __restrict__ b1) {
    __shared__ float F[K1 * 6];
    int bs = blockIdx.x, t = threadIdx.x;
    l1_gather(F, xyz, bs, bs / S1, t);
    __syncthreads();
    float w[6];
#pragma unroll
    for (int j = 0; j < 6; j++) w[j] = w1[j * C1 + t];
    float bias = b1[t];
    double ds = 0.0, dq = 0.0;
#pragma unroll 4
    for (int k = 0; k < K1; k++) {
        float h = l1_h(F + k * 6, w, bias);
        ds += (double)h;
        dq += (double)h * (double)h;
    }
    atomicAdd(&g_sums[t], ds);
    atomicAdd(&g_sums[SMAX + t], dq);
}

// ---------------- BN statistics: mu, rsqrt(var + eps) ----------------
__global__ void k_stats(int C, double M) {
    int t = blockIdx.x * blockDim.x + threadIdx.x;
    if (t >= C) return;
    double m = g_sums[t] / M;
    double var = g_sums[SMAX + t] / M - m * m;
    float vf = (float)var;
    g_mu[t] = (float)m;
    g_rs[t] = (float)(1.0 / sqrt((double)__fadd_rn(vf, 1e-5f)));
}

// ---------------- level-1 pass B: recompute h (bit-identical), normalize+relu+max ----------------
__global__ void k_nm1(const float* __restrict__ xyz,
                      const float* __restrict__ w1, const float* __restrict__ b1,
                      const float* __restrict__ g1, const float* __restrict__ be1) {
    __shared__ float F[K1 * 6];
    int bs = blockIdx.x, t = threadIdx.x;
    l1_gather(F, xyz, bs, bs / S1, t);
    __syncthreads();
    float w[6];
#pragma unroll
    for (int j = 0; j < 6; j++) w[j] = w1[j * C1 + t];
    float bias = b1[t];
    float mu = g_mu[t], rs = g_rs[t], ga = g1[t], be = be1[t];
    float m = __int_as_float(0xff800000);
#pragma unroll 4
    for (int k = 0; k < K1; k++) {
        float h = l1_h(F + k * 6, w, bias);
        float v = __fadd_rn(__fmul_rn(__fmul_rn(__fsub_rn(h, mu), rs), ga), be);
        m = fmaxf(m, fmaxf(v, 0.0f));
    }
    g_l1pts[(size_t)bs * C1 + t] = m;
}

// ---------------- level-2 MLP ----------------
__global__ void k_mlp2(const float* __restrict__ w2, const float* __restrict__ b2) {
    __shared__ __align__(16) float FT[131 * 16];   // FT[j][k], k-contiguous
    int bs = blockIdx.x, t = threadIdx.x;
    int b = bs / S2;
    for (int e = t; e < 131 * 16; e += blockDim.x) {
        int k = e / 131, j = e - k * 131;
        int idx = g_ball2[bs * K2 + k];
        float v;
        if (j < 3) {
            float4 p = g_cent1[b * N2 + idx];
            float4 c = g_cent2[bs];
            v = (j == 0) ? __fsub_rn(p.x, c.x)
              : (j == 1) ? __fsub_rn(p.y, c.y)
                         : __fsub_rn(p.z, c.z);
        } else {
            v = g_l1pts[(size_t)(b * N2 + idx) * C1 + (j - 3)];
        }
        FT[j * 16 + k] = v;
    }
    __syncthreads();
    if (t >= C2) return;
    float acc[16];
#pragma unroll
    for (int k = 0; k < 16; k++) acc[k] = 0.0f;
    for (int j = 0; j < 131; j++) {
        float wj = w2[j * C2 + t];
        const float4* fp = (const float4*)(FT + j * 16);
#pragma unroll
        for (int q = 0; q < 4; q++) {
            float4 fv = fp[q];
            acc[q * 4 + 0] = fmaf(fv.x, wj, acc[q * 4 + 0]);
            acc[q * 4 + 1] = fmaf(fv.y, wj, acc[q * 4 + 1]);
            acc[q * 4 + 2] = fmaf(fv.z, wj, acc[q * 4 + 2]);
            acc[q * 4 + 3] = fmaf(fv.w, wj, acc[q * 4 + 3]);
        }
    }
    float bias = b2[t];
    double ds = 0.0, dq = 0.0;
    float* op = g_h2 + (size_t)bs * K2 * C2 + t;
#pragma unroll
    for (int k = 0; k < 16; k++) {
        float h = __fadd_rn(acc[k], bias);
        op[(size_t)k * C2] = h;
        ds += (double)h;
        dq += (double)h * (double)h;
    }
    atomicAdd(&g_sums[t], ds);
    atomicAdd(&g_sums[SMAX + t], dq);
}

// ---------------- level-2 normalize + relu + max over k -> l2_pts ----------------
__global__ void k_nm2(const float* __restrict__ g2, const float* __restrict__ be2,
                      float* __restrict__ out) {
    int bs = blockIdx.x, c = threadIdx.x;
    if (c >= C2) return;
    float mu = g_mu[c], rs = g_rs[c], ga = g2[c], be = be2[c];
    const float* hp = g_h2 + (size_t)bs * K2 * C2 + c;
    float m = __int_as_float(0xff800000);
#pragma unroll
    for (int k = 0; k < K2; k++) {
        float h = hp[(size_t)k * C2];
        float v = __fadd_rn(__fmul_rn(__fmul_rn(__fsub_rn(h, mu), rs), ga), be);
        m = fmaxf(m, fmaxf(v, 0.0f));
    }
    out[(size_t)bs * C2 + c] = m;
}

// ==================================================================================
extern "C" void kernel_launch(void* const* d_in, const int* in_sizes, int n_in,
                              void* d_out, int out_size) {
    const float* xyz = (const float*)d_in[0];
    const float* w1  = (const float*)d_in[1];
    const float* b1  = (const float*)d_in[2];
    const float* g1  = (const float*)d_in[3];
    const float* be1 = (const float*)d_in[4];
    const float* w2  = (const float*)d_in[5];
    const float* b2  = (const float*)d_in[6];
    const float* g2  = (const float*)d_in[7];
    const float* be2 = (const float*)d_in[8];
    float* out = (float*)d_out;
    float* l2xyz = out;                    // (4,256,3)
    float* l2pts = out + Bb * S2 * 3;      // (4,256,693)

    void *pP1, *pSP, *pC1, *pC2, *pF1, *pF2, *pB1, *pB2;
    cudaGetSymbolAddress(&pP1, g_pack1);
    cudaGetSymbolAddress(&pSP, g_spts);
    cudaGetSymbolAddress(&pC1, g_cent1);
    cudaGetSymbolAddress(&pC2, g_cent2);
    cudaGetSymbolAddress(&pF1, g_fps1);
    cudaGetSymbolAddress(&pF2, g_fps2);
    cudaGetSymbolAddress(&pB1, g_ball1);
    cudaGetSymbolAddress(&pB2, g_ball2);
    float4* P1 = (float4*)pP1;
    float4* SP = (float4*)pSP;
    float4* Cn1 = (float4*)pC1;
    float4* Cn2 = (float4*)pC2;
    int* F1 = (int*)pF1;
    int* F2 = (int*)pF2;
    int* Ball1 = (int*)pB1;
    int* Ball2 = (int*)pB2;

    const float r2_1 = (float)(0.0025 * 0.0025);
    const float r2_2 = (float)(0.005 * 0.005);

    // FPS1 dynamic smem: coords 3N + oidx N + cbox + cache
    const int smem1 = (3 * N1 + N1) * (int)sizeof(float) + NCH * 6 * (int)sizeof(float)
                    + NCH * (int)sizeof(ull);                 // ~132 KB
    const int smem2 = 3 * N2 * (int)sizeof(float);            // 24 KB
    cudaFuncSetAttribute((const void*)k_fpsp,
                         cudaFuncAttributeMaxDynamicSharedMemorySize, smem1);
    cudaFuncSetAttribute((const void*)k_fps<N2, S2, 512, 4>,
                         cudaFuncAttributeMaxDynamicSharedMemorySize, smem2);

    // ---- level 1 ----
    k_pack1<<<(Bb * N1 + 255) / 256, 256>>>(xyz, P1);
    k_zeroh<<<(Bb * NCELL + 255) / 256, 256>>>();
    k_cellhist<<<(Bb * N1 + 255) / 256, 256>>>(P1);
    k_cellscan<<<Bb, NCELL>>>();
    k_scatter<<<(Bb * N1 + 255) / 256, 256>>>(P1, SP);
    k_fpsp<<<Bb, TFP, smem1>>>(SP, F1);
    k_gather<<<(Bb * S1 + 255) / 256, 256>>>(P1, F1, Cn1, S1, N1, nullptr);
    k_ball<N1, K1><<<(Bb * S1) / 8, 256>>>(P1, Cn1, S1, r2_1, Ball1);
    k_zero<<<2, 704>>>();
    k_mlp1<<<Bb * S1, C1>>>(xyz, w1, b1);
    k_stats<<<1, 704>>>(C1, (double)(Bb * S1 * K1));
    k_nm1<<<Bb * S1, C1>>>(xyz, w1, b1, g1, be1);

    // ---- level 2 ----
    k_fps<N2, S2, 512, 4><<<Bb, 512, smem2>>>(Cn1, F2);
    k_gather<<<(Bb * S2 + 255) / 256, 256>>>(Cn1, F2, Cn2, S2, N2, l2xyz);
    k_ball<N2, K2><<<(Bb * S2) / 8, 256>>>(Cn1, Cn2, S2, r2_2, Ball2);
    k_zero<<<2, 704>>>();
    k_mlp2<<<Bb * S2, 704>>>(w2, b2);
    k_stats<<<1, 704>>>(C2, (double)(Bb * S2 * K2));
    k_nm2<<<Bb * S2, 704>>>(g2, be2, l2pts);
}

// round 13
// speedup vs baseline: 1.8666x; 1.8666x over previous
#include <cuda_runtime.h>
#include <cstdint>

#define FULLMASK 0xffffffffu
typedef unsigned long long ull;

constexpr int Bb = 4;
constexpr int N1 = 8192, S1 = 2048, K1 = 32, C1 = 128;
constexpr int N2 = 2048, S2 = 256,  K2 = 16, C2 = 693;
constexpr int SMAX = 693;
constexpr int NCELL = 512;       // 8x8x8 spatial cells
constexpr int TFP = 512;         // FPS1 threads
constexpr int PPTF = 16;         // points per thread (register-resident chunk)

// ------------- static device scratch (no runtime allocation allowed) -------------
__device__ float4 g_pack1[Bb * N1];     // (x,y,z,||p||^2) level-1 coords
__device__ float4 g_spts[Bb * N1];      // spatially sorted (x,y,z,oidx-bits)
__device__ int    g_hist[Bb * NCELL];
__device__ int    g_cellofs[Bb * NCELL];
__device__ float4 g_cent1[Bb * S1];     // l1 centers (= l1_xyz), with norms
__device__ float4 g_cent2[Bb * S2];     // l2 centers
__device__ int    g_fps1[Bb * S1];
__device__ int    g_fps2[Bb * S2];
__device__ int    g_ball1[Bb * S1 * K1];
__device__ int    g_ball2[Bb * S2 * K2];
__device__ float  g_h2[(size_t)Bb * S2 * K2 * C2];   // ~45 MB
__device__ float  g_l1pts[(size_t)Bb * S1 * C1];
__device__ double g_sums[2 * SMAX];
__device__ float  g_mu[SMAX];
__device__ float  g_rs[SMAX];

// ---------------- packed f32x2 helpers (each lane = IEEE rn op, identical to scalar) ----------------
__device__ __forceinline__ ull pk2(float a, float b) {
    ull r; asm("mov.b64 %0,{%1,%2};" : "=l"(r) : "f"(a), "f"(b)); return r;
}
__device__ __forceinline__ void upk2(ull v, float& a, float& b) {
    asm("mov.b64 {%0,%1},%2;" : "=f"(a), "=f"(b) : "l"(v));
}
__device__ __forceinline__ ull f2add(ull a, ull b) {
    ull r; asm("add.rn.f32x2 %0,%1,%2;" : "=l"(r) : "l"(a), "l"(b)); return r;
}
__device__ __forceinline__ ull f2mul(ull a, ull b) {
    ull r; asm("mul.rn.f32x2 %0,%1,%2;" : "=l"(r) : "l"(a), "l"(b)); return r;
}

// (x^2 + y^2) + z^2 with explicit rounding (no FMA contraction) — matches
// XLA's elementwise mul + sequential axis(-1) reduce.
__device__ __forceinline__ float sq3(float x, float y, float z) {
    return __fadd_rn(__fadd_rn(__fmul_rn(x, x), __fmul_rn(y, y)), __fmul_rn(z, z));
}

// ---------------- pack coords + squared norm ----------------
__global__ void k_pack1(const float* __restrict__ xyz, float4* __restrict__ pack) {
    int i = blockIdx.x * blockDim.x + threadIdx.x;
    if (i >= Bb * N1) return;
    float x = xyz[(size_t)i * 6 + 0];
    float y = xyz[(size_t)i * 6 + 1];
    float z = xyz[(size_t)i * 6 + 2];
    pack[i] = make_float4(x, y, z, sq3(x, y, z));
}

// ---------------- spatial counting sort (cells 8x8x8 over [0,1)^3) ----------------
__device__ __forceinline__ int cell_of(float x, float y, float z) {
    int cx = min(7, max(0, (int)(x * 8.0f)));
    int cy = min(7, max(0, (int)(y * 8.0f)));
    int cz = min(7, max(0, (int)(z * 8.0f)));
    return (cx << 6) | (cy << 3) | cz;
}
__global__ void k_zeroh() {
    int i = blockIdx.x * blockDim.x + threadIdx.x;
    if (i < Bb * NCELL) g_hist[i] = 0;
}
__global__ void k_cellhist(const float4* __restrict__ pack) {
    int i = blockIdx.x * blockDim.x + threadIdx.x;
    if (i >= Bb * N1) return;
    float4 v = pack[i];
    atomicAdd(&g_hist[(i / N1) * NCELL + cell_of(v.x, v.y, v.z)], 1);
}
__global__ void k_cellscan() {
    __shared__ int s[NCELL];
    int b = blockIdx.x, t = threadIdx.x;
    int h = g_hist[b * NCELL + t];
    s[t] = h;
    __syncthreads();
    for (int off = 1; off < NCELL; off <<= 1) {
        int v = (t >= off) ? s[t - off] : 0;
        __syncthreads();
        s[t] += v;
        __syncthreads();
    }
    g_cellofs[b * NCELL + t] = s[t] - h;   // exclusive prefix
}
__global__ void k_scatter(const float4* __restrict__ pack, float4* __restrict__ spts) {
    int i = blockIdx.x * blockDim.x + threadIdx.x;
    if (i >= Bb * N1) return;
    int b = i / N1;
    float4 v = pack[i];
    int pos = atomicAdd(&g_cellofs[b * NCELL + cell_of(v.x, v.y, v.z)], 1);
    spts[b * N1 + pos] = make_float4(v.x, v.y, v.z, __int_as_float(i - b * N1));
}

// ---------------- FPS level 1: per-THREAD register chunks with value-safe pruning ----------------
// Thread t owns sorted positions [t*16, t*16+16) (spatially compact after the
// cell sort). It keeps coords (f32x2-packed), dd[16], its bbox, and vmax=max(dd)
// all in registers. Per iteration: 1 bbox test; skip iff dmin2*0.998 > vmax
// (then every fmin would be a no-op -> skipping is BIT-EXACT; the 0.2% margin
// dominates the ~1e-6 rel rounding of both sides). Dirty warps re-run the
// reference's exact no-FMA sub/mul/add chain (packed f32x2, per-lane identical).
// Argmax: value-only block reduce, then only the matching warp scans for the
// lowest ORIGINAL index (jnp.argmax tie semantics). Scatter order within a cell
// is nondeterministic but the result is order-invariant.
__global__ void __launch_bounds__(TFP) k_fpsp(const float4* __restrict__ spts,
                                              int* __restrict__ outIdx) {
    constexpr int N = N1, S = S1, T = TFP;
    constexpr int NW = T / 32;                 // 16 warps
    extern __shared__ float sm[];
    float* sx = sm;
    float* sy = sm + N;
    float* sz = sm + 2 * N;
    int*   soidx = (int*)(sm + 3 * N);
    __shared__ unsigned swv[NW];
    __shared__ int swi[NW];
    __shared__ int s_f0;

    int b = blockIdx.x, t = threadIdx.x;
    int w = t >> 5, l = t & 31;
    const float4* p = spts + (size_t)b * N;

    for (int i = t; i < N; i += T) {
        float4 v = p[i];
        sx[i] = v.x; sy[i] = v.y; sz[i] = v.z;
        int oi = __float_as_int(v.w);
        soidx[i] = oi;
        if (oi == 0) s_f0 = i;
    }
    __syncthreads();

    const int base = t * PPTF;
    ull px2[PPTF / 2], py2[PPTF / 2], pz2[PPTF / 2];
    float dd[PPTF];
    float bx0 = 1e30f, bx1 = -1e30f, by0 = 1e30f, by1 = -1e30f, bz0 = 1e30f, bz1 = -1e30f;
#pragma unroll
    for (int q = 0; q < PPTF / 2; q++) {
        float x0 = sx[base + 2 * q], x1 = sx[base + 2 * q + 1];
        float y0 = sy[base + 2 * q], y1 = sy[base + 2 * q + 1];
        float z0 = sz[base + 2 * q], z1 = sz[base + 2 * q + 1];
        px2[q] = pk2(x0, x1); py2[q] = pk2(y0, y1); pz2[q] = pk2(z0, z1);
        bx0 = fminf(bx0, fminf(x0, x1)); bx1 = fmaxf(bx1, fmaxf(x0, x1));
        by0 = fminf(by0, fminf(y0, y1)); by1 = fmaxf(by1, fmaxf(y0, y1));
        bz0 = fminf(bz0, fminf(z0, z1)); bz1 = fmaxf(bz1, fmaxf(z0, z1));
        dd[2 * q] = 1e10f; dd[2 * q + 1] = 1e10f;
    }
    float vmax = 1e10f;

    int* oi = outIdx + b * S;
    int f = s_f0;    // sorted position of original index 0
    int wo = 0;      // original index to emit
    for (int it = 0; it < S; ++it) {
        if (t == 0) oi[it] = wo;
        float cx = sx[f], cy = sy[f], cz = sz[f];

        // value-safe pruning test (registers only)
        float dxm = fmaxf(fmaxf(bx0 - cx, cx - bx1), 0.0f);
        float dym = fmaxf(fmaxf(by0 - cy, cy - by1), 0.0f);
        float dzm = fmaxf(fmaxf(bz0 - cz, cz - bz1), 0.0f);
        float dmin2 = dxm * dxm + dym * dym + dzm * dzm;
        bool dirty = !(dmin2 * 0.998f > vmax);

        if (__any_sync(FULLMASK, dirty)) {
            if (dirty) {
                ull ncx = pk2(-cx, -cx), ncy = pk2(-cy, -cy), ncz = pk2(-cz, -cz);
                float nm = __int_as_float(0xff800000);
#pragma unroll
                for (int q = 0; q < PPTF / 2; q++) {
                    ull dx = f2add(px2[q], ncx);
                    ull dy = f2add(py2[q], ncy);
                    ull dz = f2add(pz2[q], ncz);
                    ull s = f2add(f2add(f2mul(dx, dx), f2mul(dy, dy)), f2mul(dz, dz));
                    float d0, d1; upk2(s, d0, d1);
                    float n0 = fminf(dd[2 * q], d0);
                    float n1 = fminf(dd[2 * q + 1], d1);
                    dd[2 * q] = n0; dd[2 * q + 1] = n1;
                    nm = fmaxf(nm, fmaxf(n0, n1));
                }
                vmax = nm;
            }
        }

        // block argmax, value first (dd >= 0 -> float bits order-preserving)
        unsigned vb = __float_as_uint(vmax);
        unsigned wmax = __reduce_max_sync(FULLMASK, vb);
        if (l == 0) swv[w] = wmax;
        __syncthreads();                       // bar1: swv ready; also fences swi reads of prev iter
        unsigned gv = swv[0];
#pragma unroll
        for (int k = 1; k < NW; k++) gv = max(gv, swv[k]);

        // index recovery: only the warp(s) holding the winner scan their points
        int cand = 0x7fffffff;
        if (__any_sync(FULLMASK, vb == gv)) {
            if (vb == gv) {
#pragma unroll
                for (int j = 0; j < PPTF; j++)
                    if (__float_as_uint(dd[j]) == gv)
                        cand = min(cand, (soidx[base + j] << 13) | (base + j));
            }
            cand = __reduce_min_sync(FULLMASK, cand);
        }
        if (l == 0) swi[w] = cand;
        __syncthreads();                       // bar2: swi ready; also fences swv reads
        int key = swi[0];
#pragma unroll
        for (int k = 1; k < NW; k++) key = min(key, swi[k]);
        f = key & 0x1fff;
        wo = key >> 13;
    }
}

// ---------------- FPS (single CTA per batch) — level 2 ----------------
template <int N, int S, int T, int PPT>
__global__ void __launch_bounds__(T) k_fps(const float4* __restrict__ pack,
                                           int* __restrict__ outIdx) {
    extern __shared__ float sm[];
    float* sx = sm; float* sy = sm + N; float* sz = sm + 2 * N;
    __shared__ unsigned sv[2][32];
    __shared__ int si[2][32];
    constexpr int NP = PPT / 2;
    constexpr int NW = T / 32;
    int b = blockIdx.x, t = threadIdx.x;
    const float4* p = pack + (size_t)b * N;

    ull px2[NP], py2[NP], pz2[NP];
    float dd[PPT];
    {
        float pxs[PPT], pys[PPT], pzs[PPT];
#pragma unroll
        for (int j = 0; j < PPT; j++) {
            int i = t + j * T;
            float4 v = p[i];
            sx[i] = v.x; sy[i] = v.y; sz[i] = v.z;
            pxs[j] = v.x; pys[j] = v.y; pzs[j] = v.z;
            dd[j] = 1e10f;
        }
#pragma unroll
        for (int q = 0; q < NP; q++) {
            px2[q] = pk2(pxs[2 * q], pxs[2 * q + 1]);
            py2[q] = pk2(pys[2 * q], pys[2 * q + 1]);
            pz2[q] = pk2(pzs[2 * q], pzs[2 * q + 1]);
        }
    }
    __syncthreads();

    int* oi = outIdx + b * S;
    int lane = t & 31, wid = t >> 5;
    int f = 0;
    for (int it = 0; it < S; ++it) {
        if (t == 0) oi[it] = f;
        float cx = sx[f], cy = sy[f], cz = sz[f];
        ull ncx = pk2(-cx, -cx), ncy = pk2(-cy, -cy), ncz = pk2(-cz, -cz);
        float m = __int_as_float(0xff800000);
#pragma unroll
        for (int q = 0; q < NP; q++) {
            ull dx = f2add(px2[q], ncx);
            ull dy = f2add(py2[q], ncy);
            ull dz = f2add(pz2[q], ncz);
            ull s = f2add(f2add(f2mul(dx, dx), f2mul(dy, dy)), f2mul(dz, dz));
            float lo, hi; upk2(s, lo, hi);
            float n0 = fminf(dd[2 * q], lo);
            float n1 = fminf(dd[2 * q + 1], hi);
            dd[2 * q] = n0; dd[2 * q + 1] = n1;
            m = fmaxf(m, fmaxf(n0, n1));
        }
        unsigned mbv = __float_as_uint(m);
        unsigned wmax = __reduce_max_sync(FULLMASK, mbv);
        int cand = 0x7fffffff;
        if (mbv == wmax) {
#pragma unroll
            for (int j = PPT - 1; j >= 0; j--)
                if (__float_as_uint(dd[j]) == wmax) cand = t + j * T;
        }
        int wi = __reduce_min_sync(FULLMASK, cand);
        int par = it & 1;
        if (lane == 0) { sv[par][wid] = wmax; si[par][wid] = wi; }
        __syncthreads();
        unsigned u2 = (lane < NW) ? sv[par][lane] : 0u;
        int i2 = (lane < NW) ? si[par][lane] : 0x7fffffff;
        unsigned m2 = __reduce_max_sync(FULLMASK, u2);
        f = __reduce_min_sync(FULLMASK, (u2 == m2) ? i2 : 0x7fffffff);
    }
}

// ---------------- gather sampled centers (and optionally emit l2_xyz) ----------------
__global__ void k_gather(const float4* __restrict__ pack, const int* __restrict__ fps,
                         float4* __restrict__ cent, int S, int N,
                         float* __restrict__ xyzOut) {
    int i = blockIdx.x * blockDim.x + threadIdx.x;
    if (i >= Bb * S) return;
    int b = i / S;
    float4 v = pack[b * N + fps[i]];
    cent[i] = v;
    if (xyzOut) {
        xyzOut[(size_t)i * 3 + 0] = v.x;
        xyzOut[(size_t)i * 3 + 1] = v.y;
        xyzOut[(size_t)i * 3 + 2] = v.z;
    }
}

// ---------------- ball query: one warp per center ----------------
template <int NPTS, int K>
__global__ void k_ball(const float4* __restrict__ pack, const float4* __restrict__ cent,
                       int S, float r2, int* __restrict__ out) {
    int lane = threadIdx.x & 31;
    int cid = (blockIdx.x * blockDim.x + threadIdx.x) >> 5;
    if (cid >= Bb * S) return;
    int b = cid / S;
    float4 c = cent[cid];
    const float4* p = pack + (size_t)b * NPTS;
    int* o = out + (size_t)cid * K;
    int cnt = 0, first = -1;
    for (int base = 0; base < NPTS && cnt < K; base += 128) {
        float4 q[4];
#pragma unroll
        for (int u = 0; u < 4; u++) q[u] = p[base + u * 32 + lane];
#pragma unroll
        for (int u = 0; u < 4; u++) {
            float dot = fmaf(c.z, q[u].z, fmaf(c.y, q[u].y, __fmul_rn(c.x, q[u].x)));
            float sq = __fsub_rn(__fadd_rn(c.w, q[u].w), __fmul_rn(2.0f, dot));
            bool in = !(sq > r2);
            unsigned bm = __ballot_sync(FULLMASK, in);
            if (bm) {
                int pos = cnt + __popc(bm & ((1u << lane) - 1u));
                if (in && pos < K) o[pos] = base + u * 32 + lane;
                if (first < 0) first = base + u * 32 + __ffs(bm) - 1;
                cnt += __popc(bm);
            }
        }
    }
    if (first < 0) first = NPTS - 1;   // empty ball: idx n, clamped at gather
    for (int pos = min(cnt, K) + lane; pos < K; pos += 32) o[pos] = first;
}

// ---------------- zero the BN accumulators ----------------
__global__ void k_zero() {
    int i = blockIdx.x * blockDim.x + threadIdx.x;
    if (i < 2 * SMAX) g_sums[i] = 0.0;
}

// ---------------- level-1 feature gather (shared by both passes) ----------------
__device__ __forceinline__ void l1_gather(float* F, const float* __restrict__ xyz,
                                          int bs, int b, int t) {
    if (t < K1) {
        int idx = g_ball1[bs * K1 + t];
        float4 p = g_pack1[b * N1 + idx];
        float4 c = g_cent1[bs];
        const float* nr = xyz + (size_t)(b * N1 + idx) * 6 + 3;
        F[t * 6 + 0] = __fsub_rn(p.x, c.x);
        F[t * 6 + 1] = __fsub_rn(p.y, c.y);
        F[t * 6 + 2] = __fsub_rn(p.z, c.z);
        F[t * 6 + 3] = nr[0];
        F[t * 6 + 4] = nr[1];
        F[t * 6 + 5] = nr[2];
    }
}

__device__ __forceinline__ float l1_h(const float* fv, const float* w, float bias) {
    float h = fmaf(fv[0], w[0], 0.0f);
#pragma unroll
    for (int j = 1; j < 6; j++) h = fmaf(fv[j], w[j], h);
    return __fadd_rn(h, bias);
}

// ---------------- level-1 MLP pass A: statistics only ----------------
__global__ void k_mlp1(const float* __restrict__ xyz,
                       const float* __restrict__ w1, const float* __restrict__ b1) {
    __shared__ float F[K1 * 6];
    int bs = blockIdx.x, t = threadIdx.x;
    l1_gather(F, xyz, bs, bs / S1, t);
    __syncthreads();
    float w[6];
#pragma unroll
    for (int j = 0; j < 6; j++) w[j] = w1[j * C1 + t];
    float bias = b1[t];
    double ds = 0.0, dq = 0.0;
#pragma unroll 4
    for (int k = 0; k < K1; k++) {
        float h = l1_h(F + k * 6, w, bias);
        ds += (double)h;
        dq += (double)h * (double)h;
    }
    atomicAdd(&g_sums[t], ds);
    atomicAdd(&g_sums[SMAX + t], dq);
}

// ---------------- BN statistics: mu, rsqrt(var + eps) ----------------
__global__ void k_stats(int C, double M) {
    int t = blockIdx.x * blockDim.x + threadIdx.x;
    if (t >= C) return;
    double m = g_sums[t] / M;
    double var = g_sums[SMAX + t] / M - m * m;
    float vf = (float)var;
    g_mu[t] = (float)m;
    g_rs[t] = (float)(1.0 / sqrt((double)__fadd_rn(vf, 1e-5f)));
}

// ---------------- level-1 pass B: recompute h (bit-identical), normalize+relu+max ----------------
__global__ void k_nm1(const float* __restrict__ xyz,
                      const float* __restrict__ w1, const float* __restrict__ b1,
                      const float* __restrict__ g1, const float* __restrict__ be1) {
    __shared__ float F[K1 * 6];
    int bs = blockIdx.x, t = threadIdx.x;
    l1_gather(F, xyz, bs, bs / S1, t);
    __syncthreads();
    float w[6];
#pragma unroll
    for (int j = 0; j < 6; j++) w[j] = w1[j * C1 + t];
    float bias = b1[t];
    float mu = g_mu[t], rs = g_rs[t], ga = g1[t], be = be1[t];
    float m = __int_as_float(0xff800000);
#pragma unroll 4
    for (int k = 0; k < K1; k++) {
        float h = l1_h(F + k * 6, w, bias);
        float v = __fadd_rn(__fmul_rn(__fmul_rn(__fsub_rn(h, mu), rs), ga), be);
        m = fmaxf(m, fmaxf(v, 0.0f));
    }
    g_l1pts[(size_t)bs * C1 + t] = m;
}

// ---------------- level-2 MLP ----------------
__global__ void k_mlp2(const float* __restrict__ w2, const float* __restrict__ b2) {
    __shared__ __align__(16) float FT[131 * 16];   // FT[j][k], k-contiguous
    int bs = blockIdx.x, t = threadIdx.x;
    int b = bs / S2;
    for (int e = t; e < 131 * 16; e += blockDim.x) {
        int k = e / 131, j = e - k * 131;
        int idx = g_ball2[bs * K2 + k];
        float v;
        if (j < 3) {
            float4 p = g_cent1[b * N2 + idx];
            float4 c = g_cent2[bs];
            v = (j == 0) ? __fsub_rn(p.x, c.x)
              : (j == 1) ? __fsub_rn(p.y, c.y)
                         : __fsub_rn(p.z, c.z);
        } else {
            v = g_l1pts[(size_t)(b * N2 + idx) * C1 + (j - 3)];
        }
        FT[j * 16 + k] = v;
    }
    __syncthreads();
    if (t >= C2) return;
    float acc[16];
#pragma unroll
    for (int k = 0; k < 16; k++) acc[k] = 0.0f;
    for (int j = 0; j < 131; j++) {
        float wj = w2[j * C2 + t];
        const float4* fp = (const float4*)(FT + j * 16);
#pragma unroll
        for (int q = 0; q < 4; q++) {
            float4 fv = fp[q];
            acc[q * 4 + 0] = fmaf(fv.x, wj, acc[q * 4 + 0]);
            acc[q * 4 + 1] = fmaf(fv.y, wj, acc[q * 4 + 1]);
            acc[q * 4 + 2] = fmaf(fv.z, wj, acc[q * 4 + 2]);
            acc[q * 4 + 3] = fmaf(fv.w, wj, acc[q * 4 + 3]);
        }
    }
    float bias = b2[t];
    double ds = 0.0, dq = 0.0;
    float* op = g_h2 + (size_t)bs * K2 * C2 + t;
#pragma unroll
    for (int k = 0; k < 16; k++) {
        float h = __fadd_rn(acc[k], bias);
        op[(size_t)k * C2] = h;
        ds += (double)h;
        dq += (double)h * (double)h;
    }
    atomicAdd(&g_sums[t], ds);
    atomicAdd(&g_sums[SMAX + t], dq);
}

// ---------------- level-2 normalize + relu + max over k -> l2_pts ----------------
__global__ void k_nm2(const float* __restrict__ g2, const float* __restrict__ be2,
                      float* __restrict__ out) {
    int bs = blockIdx.x, c = threadIdx.x;
    if (c >= C2) return;
    float mu = g_mu[c], rs = g_rs[c], ga = g2[c], be = be2[c];
    const float* hp = g_h2 + (size_t)bs * K2 * C2 + c;
    float m = __int_as_float(0xff800000);
#pragma unroll
    for (int k = 0; k < K2; k++) {
        float h = hp[(size_t)k * C2];
        float v = __fadd_rn(__fmul_rn(__fmul_rn(__fsub_rn(h, mu), rs), ga), be);
        m = fmaxf(m, fmaxf(v, 0.0f));
    }
    out[(size_t)bs * C2 + c] = m;
}

// ==================================================================================
extern "C" void kernel_launch(void* const* d_in, const int* in_sizes, int n_in,
                              void* d_out, int out_size) {
    const float* xyz = (const float*)d_in[0];
    const float* w1  = (const float*)d_in[1];
    const float* b1  = (const float*)d_in[2];
    const float* g1  = (const float*)d_in[3];
    const float* be1 = (const float*)d_in[4];
    const float* w2  = (const float*)d_in[5];
    const float* b2  = (const float*)d_in[6];
    const float* g2  = (const float*)d_in[7];
    const float* be2 = (const float*)d_in[8];
    float* out = (float*)d_out;
    float* l2xyz = out;                    // (4,256,3)
    float* l2pts = out + Bb * S2 * 3;      // (4,256,693)

    void *pP1, *pSP, *pC1, *pC2, *pF1, *pF2, *pB1, *pB2;
    cudaGetSymbolAddress(&pP1, g_pack1);
    cudaGetSymbolAddress(&pSP, g_spts);
    cudaGetSymbolAddress(&pC1, g_cent1);
    cudaGetSymbolAddress(&pC2, g_cent2);
    cudaGetSymbolAddress(&pF1, g_fps1);
    cudaGetSymbolAddress(&pF2, g_fps2);
    cudaGetSymbolAddress(&pB1, g_ball1);
    cudaGetSymbolAddress(&pB2, g_ball2);
    float4* P1 = (float4*)pP1;
    float4* SP = (float4*)pSP;
    float4* Cn1 = (float4*)pC1;
    float4* Cn2 = (float4*)pC2;
    int* F1 = (int*)pF1;
    int* F2 = (int*)pF2;
    int* Ball1 = (int*)pB1;
    int* Ball2 = (int*)pB2;

    const float r2_1 = (float)(0.0025 * 0.0025);
    const float r2_2 = (float)(0.005 * 0.005);

    const int smem1 = 4 * N1 * (int)sizeof(float);            // 128 KB (coords + oidx)
    const int smem2 = 3 * N2 * (int)sizeof(float);            // 24 KB
    cudaFuncSetAttribute((const void*)k_fpsp,
                         cudaFuncAttributeMaxDynamicSharedMemorySize, smem1);
    cudaFuncSetAttribute((const void*)k_fps<N2, S2, 512, 4>,
                         cudaFuncAttributeMaxDynamicSharedMemorySize, smem2);

    // ---- level 1 ----
    k_pack1<<<(Bb * N1 + 255) / 256, 256>>>(xyz, P1);
    k_zeroh<<<(Bb * NCELL + 255) / 256, 256>>>();
    k_cellhist<<<(Bb * N1 + 255) / 256, 256>>>(P1);
    k_cellscan<<<Bb, NCELL>>>();
    k_scatter<<<(Bb * N1 + 255) / 256, 256>>>(P1, SP);
    k_fpsp<<<Bb, TFP, smem1>>>(SP, F1);
    k_gather<<<(Bb * S1 + 255) / 256, 256>>>(P1, F1, Cn1, S1, N1, nullptr);
    k_ball<N1, K1><<<(Bb * S1) / 8, 256>>>(P1, Cn1, S1, r2_1, Ball1);
    k_zero<<<2, 704>>>();
    k_mlp1<<<Bb * S1, C1>>>(xyz, w1, b1);
    k_stats<<<1, 704>>>(C1, (double)(Bb * S1 * K1));
    k_nm1<<<Bb * S1, C1>>>(xyz, w1, b1, g1, be1);

    // ---- level 2 ----
    k_fps<N2, S2, 512, 4><<<Bb, 512, smem2>>>(Cn1, F2);
    k_gather<<<(Bb * S2 + 255) / 256, 256>>>(Cn1, F2, Cn2, S2, N2, l2xyz);
    k_ball<N2, K2><<<(Bb * S2) / 8, 256>>>(Cn1, Cn2, S2, r2_2, Ball2);
    k_zero<<<2, 704>>>();
    k_mlp2<<<Bb * S2, 704>>>(w2, b2);
    k_stats<<<1, 704>>>(C2, (double)(Bb * S2 * K2));
    k_nm2<<<Bb * S2, 704>>>(g2, be2, l2pts);
}

// round 14
// speedup vs baseline: 2.3766x; 1.2732x over previous
#include <cuda_runtime.h>
#include <cstdint>

#define FULLMASK 0xffffffffu
typedef unsigned long long ull;

constexpr int Bb = 4;
constexpr int N1 = 8192, S1 = 2048, K1 = 32, C1 = 128;
constexpr int N2 = 2048, S2 = 256,  K2 = 16, C2 = 693;
constexpr int SMAX = 693;
constexpr int NCELL = 512;       // 8x8x8 spatial cells (Morton order)
constexpr int TFP = 1024;        // FPS1 threads
constexpr int PPTF = 8;          // points per thread (register-resident chunk)

// ------------- static device scratch (no runtime allocation allowed) -------------
__device__ float4 g_pack1[Bb * N1];     // (x,y,z,||p||^2) level-1 coords
__device__ float4 g_spts[Bb * N1];      // spatially sorted (x,y,z,oidx-bits)
__device__ int    g_hist[Bb * NCELL];
__device__ int    g_cellofs[Bb * NCELL];
__device__ float4 g_cent1[Bb * S1];     // l1 centers (= l1_xyz), with norms
__device__ float4 g_cent2[Bb * S2];     // l2 centers
__device__ int    g_fps1[Bb * S1];
__device__ int    g_fps2[Bb * S2];
__device__ int    g_ball1[Bb * S1 * K1];
__device__ int    g_ball2[Bb * S2 * K2];
__device__ float  g_h2[(size_t)Bb * S2 * K2 * C2];   // ~45 MB
__device__ float  g_l1pts[(size_t)Bb * S1 * C1];
__device__ double g_sums[2 * SMAX];
__device__ float  g_mu[SMAX];
__device__ float  g_rs[SMAX];

// ---------------- packed f32x2 helpers (each lane = IEEE rn op, identical to scalar) ----------------
__device__ __forceinline__ ull pk2(float a, float b) {
    ull r; asm("mov.b64 %0,{%1,%2};" : "=l"(r) : "f"(a), "f"(b)); return r;
}
__device__ __forceinline__ void upk2(ull v, float& a, float& b) {
    asm("mov.b64 {%0,%1},%2;" : "=f"(a), "=f"(b) : "l"(v));
}
__device__ __forceinline__ ull f2add(ull a, ull b) {
    ull r; asm("add.rn.f32x2 %0,%1,%2;" : "=l"(r) : "l"(a), "l"(b)); return r;
}
__device__ __forceinline__ ull f2mul(ull a, ull b) {
    ull r; asm("mul.rn.f32x2 %0,%1,%2;" : "=l"(r) : "l"(a), "l"(b)); return r;
}

// (x^2 + y^2) + z^2 with explicit rounding (no FMA contraction) — matches
// XLA's elementwise mul + sequential axis(-1) reduce.
__device__ __forceinline__ float sq3(float x, float y, float z) {
    return __fadd_rn(__fadd_rn(__fmul_rn(x, x), __fmul_rn(y, y)), __fmul_rn(z, z));
}

// ---------------- pack coords + squared norm ----------------
__global__ void k_pack1(const float* __restrict__ xyz, float4* __restrict__ pack) {
    int i = blockIdx.x * blockDim.x + threadIdx.x;
    if (i >= Bb * N1) return;
    float x = xyz[(size_t)i * 6 + 0];
    float y = xyz[(size_t)i * 6 + 1];
    float z = xyz[(size_t)i * 6 + 2];
    pack[i] = make_float4(x, y, z, sq3(x, y, z));
}

// ---------------- spatial counting sort (8x8x8 cells, Morton order) ----------------
__device__ __forceinline__ int cell_of(float x, float y, float z) {
    int cx = min(7, max(0, (int)(x * 8.0f)));
    int cy = min(7, max(0, (int)(y * 8.0f)));
    int cz = min(7, max(0, (int)(z * 8.0f)));
    int m = 0;
#pragma unroll
    for (int i = 0; i < 3; i++) {
        m |= ((cz >> i) & 1) << (3 * i + 0);
        m |= ((cy >> i) & 1) << (3 * i + 1);
        m |= ((cx >> i) & 1) << (3 * i + 2);
    }
    return m;
}
__global__ void k_zeroh() {
    int i = blockIdx.x * blockDim.x + threadIdx.x;
    if (i < Bb * NCELL) g_hist[i] = 0;
}
__global__ void k_cellhist(const float4* __restrict__ pack) {
    int i = blockIdx.x * blockDim.x + threadIdx.x;
    if (i >= Bb * N1) return;
    float4 v = pack[i];
    atomicAdd(&g_hist[(i / N1) * NCELL + cell_of(v.x, v.y, v.z)], 1);
}
__global__ void k_cellscan() {
    __shared__ int s[NCELL];
    int b = blockIdx.x, t = threadIdx.x;
    int h = g_hist[b * NCELL + t];
    s[t] = h;
    __syncthreads();
    for (int off = 1; off < NCELL; off <<= 1) {
        int v = (t >= off) ? s[t - off] : 0;
        __syncthreads();
        s[t] += v;
        __syncthreads();
    }
    g_cellofs[b * NCELL + t] = s[t] - h;   // exclusive prefix
}
__global__ void k_scatter(const float4* __restrict__ pack, float4* __restrict__ spts) {
    int i = blockIdx.x * blockDim.x + threadIdx.x;
    if (i >= Bb * N1) return;
    int b = i / N1;
    float4 v = pack[i];
    int pos = atomicAdd(&g_cellofs[b * NCELL + cell_of(v.x, v.y, v.z)], 1);
    spts[b * N1 + pos] = make_float4(v.x, v.y, v.z, __int_as_float(i - b * N1));
}

// ---------------- FPS level 1: per-thread pruning + R6 reduce tail ----------------
// Thread t owns sorted positions [t*8, t*8+8) (Morton-compact). Coords packed
// f32x2, dd[8], bbox, vmax all in registers. Skip iff dmin2*0.998 > vmax:
// then every fmin is provably a no-op -> skip is BIT-EXACT (0.2% margin >>
// ~1e-6 rel rounding). Dirty warps rerun the reference's exact no-FMA chain
// for all lanes (exact values, not approximations) and refresh their
// lane-uniform (wval,wkey) candidate registers; clean warps keep theirs.
// Every warp re-stores (wval,wkey) to double-buffered smem slots each iter
// (2 STS), then one barrier + 2-redux fold. key=(oidx<<13|pos) min ->
// ties resolve to lowest ORIGINAL index (jnp.argmax semantics). Counting-sort
// scatter order is nondeterministic but result-invariant.
__global__ void __launch_bounds__(TFP) k_fpsp(const float4* __restrict__ spts,
                                              int* __restrict__ outIdx) {
    constexpr int N = N1, S = S1, T = TFP;
    constexpr int NW = T / 32;                 // 32 warps
    extern __shared__ float sm[];
    float* sx = sm;
    float* sy = sm + N;
    float* sz = sm + 2 * N;
    int*   soidx = (int*)(sm + 3 * N);
    __shared__ unsigned sv[2][NW];
    __shared__ int sk[2][NW];
    __shared__ int s_f0;

    int b = blockIdx.x, t = threadIdx.x;
    int w = t >> 5, l = t & 31;
    const float4* p = spts + (size_t)b * N;

    for (int i = t; i < N; i += T) {
        float4 v = p[i];
        sx[i] = v.x; sy[i] = v.y; sz[i] = v.z;
        int oi = __float_as_int(v.w);
        soidx[i] = oi;
        if (oi == 0) s_f0 = i;
    }
    __syncthreads();

    const int base = t * PPTF;
    ull px2[PPTF / 2], py2[PPTF / 2], pz2[PPTF / 2];
    float dd[PPTF];
    float bx0 = 1e30f, bx1 = -1e30f, by0 = 1e30f, by1 = -1e30f, bz0 = 1e30f, bz1 = -1e30f;
#pragma unroll
    for (int q = 0; q < PPTF / 2; q++) {
        float x0 = sx[base + 2 * q], x1 = sx[base + 2 * q + 1];
        float y0 = sy[base + 2 * q], y1 = sy[base + 2 * q + 1];
        float z0 = sz[base + 2 * q], z1 = sz[base + 2 * q + 1];
        px2[q] = pk2(x0, x1); py2[q] = pk2(y0, y1); pz2[q] = pk2(z0, z1);
        bx0 = fminf(bx0, fminf(x0, x1)); bx1 = fmaxf(bx1, fmaxf(x0, x1));
        by0 = fminf(by0, fminf(y0, y1)); by1 = fmaxf(by1, fmaxf(y0, y1));
        bz0 = fminf(bz0, fminf(z0, z1)); bz1 = fmaxf(bz1, fmaxf(z0, z1));
        dd[2 * q] = 1e10f; dd[2 * q + 1] = 1e10f;
    }
    float vmax = 1e10f;
    unsigned wval = 0u;          // lane-uniform warp candidate (set on iter 0: all dirty)
    int wkey = 0x7fffffff;

    int* oi = outIdx + b * S;
    int f = s_f0;    // sorted position of original index 0
    int wo = 0;      // original index to emit
    for (int it = 0; it < S; ++it) {
        if (t == 0) oi[it] = wo;
        float cx = sx[f], cy = sy[f], cz = sz[f];

        // value-safe pruning test (registers only)
        float dxm = fmaxf(fmaxf(bx0 - cx, cx - bx1), 0.0f);
        float dym = fmaxf(fmaxf(by0 - cy, cy - by1), 0.0f);
        float dzm = fmaxf(fmaxf(bz0 - cz, cz - bz1), 0.0f);
        float dmin2 = dxm * dxm + dym * dym + dzm * dzm;
        bool dirty = !(dmin2 * 0.998f > vmax);

        if (__any_sync(FULLMASK, dirty)) {
            // whole warp reruns the exact update (clean lanes: exact too)
            ull ncx = pk2(-cx, -cx), ncy = pk2(-cy, -cy), ncz = pk2(-cz, -cz);
            float nm = __int_as_float(0xff800000);
#pragma unroll
            for (int q = 0; q < PPTF / 2; q++) {
                ull dx = f2add(px2[q], ncx);
                ull dy = f2add(py2[q], ncy);
                ull dz = f2add(pz2[q], ncz);
                ull s = f2add(f2add(f2mul(dx, dx), f2mul(dy, dy)), f2mul(dz, dz));
                float d0, d1; upk2(s, d0, d1);
                float n0 = fminf(dd[2 * q], d0);
                float n1 = fminf(dd[2 * q + 1], d1);
                dd[2 * q] = n0; dd[2 * q + 1] = n1;
                nm = fmaxf(nm, fmaxf(n0, n1));
            }
            vmax = nm;
            unsigned vb = __float_as_uint(vmax);       // dd >= 0 -> order-preserving
            unsigned wm = __reduce_max_sync(FULLMASK, vb);
            int cand = 0x7fffffff;
            if (vb == wm) {
#pragma unroll
                for (int j = 0; j < PPTF; j++)
                    if (__float_as_uint(dd[j]) == wm)
                        cand = min(cand, (soidx[base + j] << 13) | (base + j));
            }
            cand = __reduce_min_sync(FULLMASK, cand);
            wval = wm; wkey = cand;                    // lane-uniform
        }

        int par = it & 1;
        if (l == 0) { sv[par][w] = wval; sk[par][w] = wkey; }
        __syncthreads();
        unsigned u2 = sv[par][l];                      // NW == 32
        unsigned gm = __reduce_max_sync(FULLMASK, u2);
        int kk = __reduce_min_sync(FULLMASK, (u2 == gm) ? sk[par][l] : 0x7fffffff);
        f = kk & 0x1fff;
        wo = kk >> 13;
    }
}

// ---------------- FPS (single CTA per batch) — level 2 ----------------
template <int N, int S, int T, int PPT>
__global__ void __launch_bounds__(T) k_fps(const float4* __restrict__ pack,
                                           int* __restrict__ outIdx) {
    extern __shared__ float sm[];
    float* sx = sm; float* sy = sm + N; float* sz = sm + 2 * N;
    __shared__ unsigned sv[2][32];
    __shared__ int si[2][32];
    constexpr int NP = PPT / 2;
    constexpr int NW = T / 32;
    int b = blockIdx.x, t = threadIdx.x;
    const float4* p = pack + (size_t)b * N;

    ull px2[NP], py2[NP], pz2[NP];
    float dd[PPT];
    {
        float pxs[PPT], pys[PPT], pzs[PPT];
#pragma unroll
        for (int j = 0; j < PPT; j++) {
            int i = t + j * T;
            float4 v = p[i];
            sx[i] = v.x; sy[i] = v.y; sz[i] = v.z;
            pxs[j] = v.x; pys[j] = v.y; pzs[j] = v.z;
            dd[j] = 1e10f;
        }
#pragma unroll
        for (int q = 0; q < NP; q++) {
            px2[q] = pk2(pxs[2 * q], pxs[2 * q + 1]);
            py2[q] = pk2(pys[2 * q], pys[2 * q + 1]);
            pz2[q] = pk2(pzs[2 * q], pzs[2 * q + 1]);
        }
    }
    __syncthreads();

    int* oi = outIdx + b * S;
    int lane = t & 31, wid = t >> 5;
    int f = 0;
    for (int it = 0; it < S; ++it) {
        if (t == 0) oi[it] = f;
        float cx = sx[f], cy = sy[f], cz = sz[f];
        ull ncx = pk2(-cx, -cx), ncy = pk2(-cy, -cy), ncz = pk2(-cz, -cz);
        float m = __int_as_float(0xff800000);
#pragma unroll
        for (int q = 0; q < NP; q++) {
            ull dx = f2add(px2[q], ncx);
            ull dy = f2add(py2[q], ncy);
            ull dz = f2add(pz2[q], ncz);
            ull s = f2add(f2add(f2mul(dx, dx), f2mul(dy, dy)), f2mul(dz, dz));
            float lo, hi; upk2(s, lo, hi);
            float n0 = fminf(dd[2 * q], lo);
            float n1 = fminf(dd[2 * q + 1], hi);
            dd[2 * q] = n0; dd[2 * q + 1] = n1;
            m = fmaxf(m, fmaxf(n0, n1));
        }
        unsigned mbv = __float_as_uint(m);
        unsigned wmax = __reduce_max_sync(FULLMASK, mbv);
        int cand = 0x7fffffff;
        if (mbv == wmax) {
#pragma unroll
            for (int j = PPT - 1; j >= 0; j--)
                if (__float_as_uint(dd[j]) == wmax) cand = t + j * T;
        }
        int wi = __reduce_min_sync(FULLMASK, cand);
        int par = it & 1;
        if (lane == 0) { sv[par][wid] = wmax; si[par][wid] = wi; }
        __syncthreads();
        unsigned u2 = (lane < NW) ? sv[par][lane] : 0u;
        int i2 = (lane < NW) ? si[par][lane] : 0x7fffffff;
        unsigned m2 = __reduce_max_sync(FULLMASK, u2);
        f = __reduce_min_sync(FULLMASK, (u2 == m2) ? i2 : 0x7fffffff);
    }
}

// ---------------- gather sampled centers (and optionally emit l2_xyz) ----------------
__global__ void k_gather(const float4* __restrict__ pack, const int* __restrict__ fps,
                         float4* __restrict__ cent, int S, int N,
                         float* __restrict__ xyzOut) {
    int i = blockIdx.x * blockDim.x + threadIdx.x;
    if (i >= Bb * S) return;
    int b = i / S;
    float4 v = pack[b * N + fps[i]];
    cent[i] = v;
    if (xyzOut) {
        xyzOut[(size_t)i * 3 + 0] = v.x;
        xyzOut[(size_t)i * 3 + 1] = v.y;
        xyzOut[(size_t)i * 3 + 2] = v.z;
    }
}

// ---------------- ball query: one warp per center ----------------
template <int NPTS, int K>
__global__ void k_ball(const float4* __restrict__ pack, const float4* __restrict__ cent,
                       int S, float r2, int* __restrict__ out) {
    int lane = threadIdx.x & 31;
    int cid = (blockIdx.x * blockDim.x + threadIdx.x) >> 5;
    if (cid >= Bb * S) return;
    int b = cid / S;
    float4 c = cent[cid];
    const float4* p = pack + (size_t)b * NPTS;
    int* o = out + (size_t)cid * K;
    int cnt = 0, first = -1;
    for (int base = 0; base < NPTS && cnt < K; base += 128) {
        float4 q[4];
#pragma unroll
        for (int u = 0; u < 4; u++) q[u] = p[base + u * 32 + lane];
#pragma unroll
        for (int u = 0; u < 4; u++) {
            float dot = fmaf(c.z, q[u].z, fmaf(c.y, q[u].y, __fmul_rn(c.x, q[u].x)));
            float sq = __fsub_rn(__fadd_rn(c.w, q[u].w), __fmul_rn(2.0f, dot));
            bool in = !(sq > r2);
            unsigned bm = __ballot_sync(FULLMASK, in);
            if (bm) {
                int pos = cnt + __popc(bm & ((1u << lane) - 1u));
                if (in && pos < K) o[pos] = base + u * 32 + lane;
                if (first < 0) first = base + u * 32 + __ffs(bm) - 1;
                cnt += __popc(bm);
            }
        }
    }
    if (first < 0) first = NPTS - 1;   // empty ball: idx n, clamped at gather
    for (int pos = min(cnt, K) + lane; pos < K; pos += 32) o[pos] = first;
}

// ---------------- zero the BN accumulators ----------------
__global__ void k_zero() {
    int i = blockIdx.x * blockDim.x + threadIdx.x;
    if (i < 2 * SMAX) g_sums[i] = 0.0;
}

// ---------------- level-1 feature gather (shared by both passes) ----------------
__device__ __forceinline__ void l1_gather(float* F, const float* __restrict__ xyz,
                                          int bs, int b, int t) {
    if (t < K1) {
        int idx = g_ball1[bs * K1 + t];
        float4 p = g_pack1[b * N1 + idx];
        float4 c = g_cent1[bs];
        const float* nr = xyz + (size_t)(b * N1 + idx) * 6 + 3;
        F[t * 6 + 0] = __fsub_rn(p.x, c.x);
        F[t * 6 + 1] = __fsub_rn(p.y, c.y);
        F[t * 6 + 2] = __fsub_rn(p.z, c.z);
        F[t * 6 + 3] = nr[0];
        F[t * 6 + 4] = nr[1];
        F[t * 6 + 5] = nr[2];
    }
}

__device__ __forceinline__ float l1_h(const float* fv, const float* w, float bias) {
    float h = fmaf(fv[0], w[0], 0.0f);
#pragma unroll
    for (int j = 1; j < 6; j++) h = fmaf(fv[j], w[j], h);
    return __fadd_rn(h, bias);
}

// ---------------- level-1 MLP pass A: statistics only ----------------
__global__ void k_mlp1(const float* __restrict__ xyz,
                       const float* __restrict__ w1, const float* __restrict__ b1) {
    __shared__ float F[K1 * 6];
    int bs = blockIdx.x, t = threadIdx.x;
    l1_gather(F, xyz, bs, bs / S1, t);
    __syncthreads();
    float w[6];
#pragma unroll
    for (int j = 0; j < 6; j++) w[j] = w1[j * C1 + t];
    float bias = b1[t];
    double ds = 0.0, dq = 0.0;
#pragma unroll 4
    for (int k = 0; k < K1; k++) {
        float h = l1_h(F + k * 6, w, bias);
        ds += (double)h;
        dq += (double)h * (double)h;
    }
    atomicAdd(&g_sums[t], ds);
    atomicAdd(&g_sums[SMAX + t], dq);
}

// ---------------- BN statistics: mu, rsqrt(var + eps) ----------------
__global__ void k_stats(int C, double M) {
    int t = blockIdx.x * blockDim.x + threadIdx.x;
    if (t >= C) return;
    double m = g_sums[t] / M;
    double var = g_sums[SMAX + t] / M - m * m;
    float vf = (float)var;
    g_mu[t] = (float)m;
    g_rs[t] = (float)(1.0 / sqrt((double)__fadd_rn(vf, 1e-5f)));
}

// ---------------- level-1 pass B: recompute h (bit-identical), normalize+relu+max ----------------
__global__ void k_nm1(const float* __restrict__ xyz,
                      const float* __restrict__ w1, const float* __restrict__ b1,
                      const float* __restrict__ g1, const float* __restrict__ be1) {
    __shared__ float F[K1 * 6];
    int bs = blockIdx.x, t = threadIdx.x;
    l1_gather(F, xyz, bs, bs / S1, t);
    __syncthreads();
    float w[6];
#pragma unroll
    for (int j = 0; j < 6; j++) w[j] = w1[j * C1 + t];
    float bias = b1[t];
    float mu = g_mu[t], rs = g_rs[t], ga = g1[t], be = be1[t];
    float m = __int_as_float(0xff800000);
#pragma unroll 4
    for (int k = 0; k < K1; k++) {
        float h = l1_h(F + k * 6, w, bias);
        float v = __fadd_rn(__fmul_rn(__fmul_rn(__fsub_rn(h, mu), rs), ga), be);
        m = fmaxf(m, fmaxf(v, 0.0f));
    }
    g_l1pts[(size_t)bs * C1 + t] = m;
}

// ---------------- level-2 MLP ----------------
__global__ void k_mlp2(const float* __restrict__ w2, const float* __restrict__ b2) {
    __shared__ __align__(16) float FT[131 * 16];   // FT[j][k], k-contiguous
    int bs = blockIdx.x, t = threadIdx.x;
    int b = bs / S2;
    for (int e = t; e < 131 * 16; e += blockDim.x) {
        int k = e / 131, j = e - k * 131;
        int idx = g_ball2[bs * K2 + k];
        float v;
        if (j < 3) {
            float4 p = g_cent1[b * N2 + idx];
            float4 c = g_cent2[bs];
            v = (j == 0) ? __fsub_rn(p.x, c.x)
              : (j == 1) ? __fsub_rn(p.y, c.y)
                         : __fsub_rn(p.z, c.z);
        } else {
            v = g_l1pts[(size_t)(b * N2 + idx) * C1 + (j - 3)];
        }
        FT[j * 16 + k] = v;
    }
    __syncthreads();
    if (t >= C2) return;
    float acc[16];
#pragma unroll
    for (int k = 0; k < 16; k++) acc[k] = 0.0f;
    for (int j = 0; j < 131; j++) {
        float wj = w2[j * C2 + t];
        const float4* fp = (const float4*)(FT + j * 16);
#pragma unroll
        for (int q = 0; q < 4; q++) {
            float4 fv = fp[q];
            acc[q * 4 + 0] = fmaf(fv.x, wj, acc[q * 4 + 0]);
            acc[q * 4 + 1] = fmaf(fv.y, wj, acc[q * 4 + 1]);
            acc[q * 4 + 2] = fmaf(fv.z, wj, acc[q * 4 + 2]);
            acc[q * 4 + 3] = fmaf(fv.w, wj, acc[q * 4 + 3]);
        }
    }
    float bias = b2[t];
    double ds = 0.0, dq = 0.0;
    float* op = g_h2 + (size_t)bs * K2 * C2 + t;
#pragma unroll
    for (int k = 0; k < 16; k++) {
        float h = __fadd_rn(acc[k], bias);
        op[(size_t)k * C2] = h;
        ds += (double)h;
        dq += (double)h * (double)h;
    }
    atomicAdd(&g_sums[t], ds);
    atomicAdd(&g_sums[SMAX + t], dq);
}

// ---------------- level-2 normalize + relu + max over k -> l2_pts ----------------
__global__ void k_nm2(const float* __restrict__ g2, const float* __restrict__ be2,
                      float* __restrict__ out) {
    int bs = blockIdx.x, c = threadIdx.x;
    if (c >= C2) return;
    float mu = g_mu[c], rs = g_rs[c], ga = g2[c], be = be2[c];
    const float* hp = g_h2 + (size_t)bs * K2 * C2 + c;
    float m = __int_as_float(0xff800000);
#pragma unroll
    for (int k = 0; k < K2; k++) {
        float h = hp[(size_t)k * C2];
        float v = __fadd_rn(__fmul_rn(__fmul_rn(__fsub_rn(h, mu), rs), ga), be);
        m = fmaxf(m, fmaxf(v, 0.0f));
    }
    out[(size_t)bs * C2 + c] = m;
}

// ==================================================================================
extern "C" void kernel_launch(void* const* d_in, const int* in_sizes, int n_in,
                              void* d_out, int out_size) {
    const float* xyz = (const float*)d_in[0];
    const float* w1  = (const float*)d_in[1];
    const float* b1  = (const float*)d_in[2];
    const float* g1  = (const float*)d_in[3];
    const float* be1 = (const float*)d_in[4];
    const float* w2  = (const float*)d_in[5];
    const float* b2  = (const float*)d_in[6];
    const float* g2  = (const float*)d_in[7];
    const float* be2 = (const float*)d_in[8];
    float* out = (float*)d_out;
    float* l2xyz = out;                    // (4,256,3)
    float* l2pts = out + Bb * S2 * 3;      // (4,256,693)

    void *pP1, *pSP, *pC1, *pC2, *pF1, *pF2, *pB1, *pB2;
    cudaGetSymbolAddress(&pP1, g_pack1);
    cudaGetSymbolAddress(&pSP, g_spts);
    cudaGetSymbolAddress(&pC1, g_cent1);
    cudaGetSymbolAddress(&pC2, g_cent2);
    cudaGetSymbolAddress(&pF1, g_fps1);
    cudaGetSymbolAddress(&pF2, g_fps2);
    cudaGetSymbolAddress(&pB1, g_ball1);
    cudaGetSymbolAddress(&pB2, g_ball2);
    float4* P1 = (float4*)pP1;
    float4* SP = (float4*)pSP;
    float4* Cn1 = (float4*)pC1;
    float4* Cn2 = (float4*)pC2;
    int* F1 = (int*)pF1;
    int* F2 = (int*)pF2;
    int* Ball1 = (int*)pB1;
    int* Ball2 = (int*)pB2;

    const float r2_1 = (float)(0.0025 * 0.0025);
    const float r2_2 = (float)(0.005 * 0.005);

    const int smem1 = 4 * N1 * (int)sizeof(float);            // 128 KB (coords + oidx)
    const int smem2 = 3 * N2 * (int)sizeof(float);            // 24 KB
    cudaFuncSetAttribute((const void*)k_fpsp,
                         cudaFuncAttributeMaxDynamicSharedMemorySize, smem1);
    cudaFuncSetAttribute((const void*)k_fps<N2, S2, 512, 4>,
                         cudaFuncAttributeMaxDynamicSharedMemorySize, smem2);

    // ---- level 1 ----
    k_pack1<<<(Bb * N1 + 255) / 256, 256>>>(xyz, P1);
    k_zeroh<<<(Bb * NCELL + 255) / 256, 256>>>();
    k_cellhist<<<(Bb * N1 + 255) / 256, 256>>>(P1);
    k_cellscan<<<Bb, NCELL>>>();
    k_scatter<<<(Bb * N1 + 255) / 256, 256>>>(P1, SP);
    k_fpsp<<<Bb, TFP, smem1>>>(SP, F1);
    k_gather<<<(Bb * S1 + 255) / 256, 256>>>(P1, F1, Cn1, S1, N1, nullptr);
    k_ball<N1, K1><<<(Bb * S1) / 8, 256>>>(P1, Cn1, S1, r2_1, Ball1);
    k_zero<<<2, 704>>>();
    k_mlp1<<<Bb * S1, C1>>>(xyz, w1, b1);
    k_stats<<<1, 704>>>(C1, (double)(Bb * S1 * K1));
    k_nm1<<<Bb * S1, C1>>>(xyz, w1, b1, g1, be1);

    // ---- level 2 ----
    k_fps<N2, S2, 512, 4><<<Bb, 512, smem2>>>(Cn1, F2);
    k_gather<<<(Bb * S2 + 255) / 256, 256>>>(Cn1, F2, Cn2, S2, N2, l2xyz);
    k_ball<N2, K2><<<(Bb * S2) / 8, 256>>>(Cn1, Cn2, S2, r2_2, Ball2);
    k_zero<<<2, 704>>>();
    k_mlp2<<<Bb * S2, 704>>>(w2, b2);
    k_stats<<<1, 704>>>(C2, (double)(Bb * S2 * K2));
    k_nm2<<<Bb * S2, 704>>>(g2, be2, l2pts);
}